// round 2
// baseline (speedup 1.0000x reference)
#include <cuda_runtime.h>
#include <math.h>
#include <stdint.h>

#define VOCAB   32000
#define EMBED   300
#define HIDDEN  1024
#define BATCH   64
#define SEQLEN  512
#define GDIM    4096   // 4*HIDDEN

#define NCTA    128    // persistent CTAs (<=148 SMs, all resident)
#define P2T     128    // threads per persistent CTA

// ---------------- device scratch (no allocations allowed) ----------------
__device__ float    g_xz[(size_t)SEQLEN * BATCH * GDIM];   // [t][b][g] fp32
__device__ float    g_hbuf[2][BATCH * HIDDEN];             // [b][j], double buffered
__device__ unsigned g_bar_count;
__device__ volatile unsigned g_bar_gen;

// packed fp32x2 FMA: d.lo += a.lo*b.lo ; d.hi += a.hi*b.hi   (sm_100+ PTX only)
__device__ __forceinline__ void ffma2(unsigned long long& d,
                                      unsigned long long a,
                                      unsigned long long b) {
    asm("fma.rn.f32x2 %0, %1, %2, %0;" : "+l"(d) : "l"(a), "l"(b));
}
__device__ __forceinline__ float usum(unsigned long long v) {
    union { unsigned long long u; float2 f; } t; t.u = v;
    return t.f.x + t.f.y;
}

// ---------------- grid barrier (all NCTA CTAs resident) ------------------
__device__ __forceinline__ void grid_barrier() {
    __syncthreads();
    if (threadIdx.x == 0) {
        __threadfence();
        unsigned g = g_bar_gen;
        if (atomicAdd(&g_bar_count, 1u) == NCTA - 1u) {
            atomicExch(&g_bar_count, 0u);
            __threadfence();
            g_bar_gen = g + 1u;
        } else {
            while (g_bar_gen == g) { __nanosleep(64); }
        }
        __threadfence();
    }
    __syncthreads();
}

// =========================================================================
// Phase 1: xz[t][b][g] = emb[seq[b][t]] @ W + bias
// M = T*B = 32768 (m = t*64 + b), K = 300, N = 4096
// K-major smem tiles + f32x2 packed FMA (pairs along K, no packing needed).
// =========================================================================
__global__ void __launch_bounds__(256) xz_gemm_kernel(
    const float* __restrict__ emb, const float* __restrict__ W,
    const float* __restrict__ bias, const int* __restrict__ seq)
{
    __shared__ __align__(16) float As[64 * 32];   // [m][k] swizzled
    __shared__ __align__(16) float Bs[64 * 32];   // [n][k] swizzled
    __shared__ int toks[64];

    const int tid = threadIdx.x;
    const int m0  = blockIdx.y * 64;
    const int n0  = blockIdx.x * 64;

    if (tid < 64) {
        int m = m0 + tid;
        toks[tid] = seq[(m & 63) * SEQLEN + (m >> 6)];
    }
    __syncthreads();

    const int tx  = tid & 15;          // col group (16)
    const int ty  = tid >> 4;          // row group (16)
    const int tx4 = tx * 4;
    const int ty4 = ty * 4;
    const int s_a = (ty & 7) << 2;     // swizzle for my A rows ((m>>2)&7)<<2
    const int s_b = (tx & 7) << 2;     // swizzle for my B rows

    unsigned long long acc[4][4];
    #pragma unroll
    for (int i = 0; i < 4; i++)
        #pragma unroll
        for (int j = 0; j < 4; j++) acc[i][j] = 0ull;

    for (int k0 = 0; k0 < EMBED; k0 += 32) {
        // --- A tile: As[m][k] = emb[tok[m]][k0+k]  (rows are k-contiguous) ---
        #pragma unroll
        for (int pass = 0; pass < 2; pass++) {
            int idx = tid + pass * 256;
            int m   = idx >> 3;
            int kk4 = (idx & 7) * 4;
            int kg  = k0 + kk4;
            float4 v = make_float4(0.f, 0.f, 0.f, 0.f);
            if (kg < EMBED)  // EMBED % 4 == 0 -> kg+3 <= 299
                v = *(const float4*)&emb[(size_t)toks[m] * EMBED + kg];
            int sw = kk4 ^ (((m >> 2) & 7) << 2);
            *(float4*)&As[m * 32 + sw] = v;
        }
        // --- B tile: Bs[n][k] = W[k0+k][n0+n]  (transposed scalar stores) ---
        #pragma unroll
        for (int pass = 0; pass < 8; pass++) {
            int n = tid & 63;
            int k = (tid >> 6) + pass * 4;
            float v = 0.f;
            if (k0 + k < EMBED)
                v = W[(size_t)(k0 + k) * GDIM + n0 + n];
            int sw = ((k & ~3) ^ (((n >> 2) & 7) << 2)) + (k & 3);
            Bs[n * 32 + sw] = v;
        }
        __syncthreads();

        #pragma unroll
        for (int kk = 0; kk < 32; kk += 4) {
            int ka = kk ^ s_a;
            int kb = kk ^ s_b;
            ulonglong2 a_[4], b_[4];
            #pragma unroll
            for (int r = 0; r < 4; r++)
                a_[r] = *(const ulonglong2*)&As[(ty4 + r) * 32 + ka];
            #pragma unroll
            for (int q = 0; q < 4; q++)
                b_[q] = *(const ulonglong2*)&Bs[(tx4 + q) * 32 + kb];
            #pragma unroll
            for (int r = 0; r < 4; r++)
                #pragma unroll
                for (int q = 0; q < 4; q++) {
                    ffma2(acc[r][q], a_[r].x, b_[q].x);
                    ffma2(acc[r][q], a_[r].y, b_[q].y);
                }
        }
        __syncthreads();
    }

    float4 bv = *(const float4*)&bias[n0 + tx4];
    #pragma unroll
    for (int r = 0; r < 4; r++) {
        float4 o;
        o.x = usum(acc[r][0]) + bv.x;
        o.y = usum(acc[r][1]) + bv.y;
        o.z = usum(acc[r][2]) + bv.z;
        o.w = usum(acc[r][3]) + bv.w;
        *(float4*)&g_xz[(size_t)(m0 + ty4 + r) * GDIM + n0 + tx4] = o;
    }
}

// =========================================================================
// Phase 2: persistent masked-LSTM scan with f32x2 packed FMA.
// CTA owns 8 hidden cols (x4 gates = 32 z cols). R slice [32 cols][1024 k]
// K-major + swizzled, resident in SMEM all 512 steps. h tiles K-major.
// =========================================================================
__global__ void __launch_bounds__(P2T, 1) lstm_kernel(
    const float* __restrict__ Rm,     // [1024][4096]
    const int*   __restrict__ seq,    // [64][512]
    float*       __restrict__ out)    // [64][1024]
{
    extern __shared__ __align__(16) float sm[];
    float* R_s = sm;                   // [32 c][1024 k] swizzled (128KB)
    float* h_s = sm + 32 * 1024;       // [64 b][128 k]  swizzled (32KB)
    float* z_s = h_s + 64 * 128;       // [64][36]

    const int tid = threadIdx.x;
    const int cta = blockIdx.x;
    const int j0  = cta * 8;

    // load persistent R slice, transposed to [c][k] with 4-word XOR swizzle
    for (int idx = tid; idx < 32 * 1024; idx += P2T) {
        int k = idx >> 5, c = idx & 31;
        int gcol = (c >> 3) * HIDDEN + j0 + (c & 7);
        int sw = ((k & ~3) ^ (((c >> 2) & 7) << 2)) + (k & 3);
        R_s[c * 1024 + sw] = Rm[(size_t)k * GDIM + gcol];
    }

    const int myb = tid >> 1;            // batch owned in gate phase
    const int jlb = (tid & 1) * 4;       // local-j base (0 or 4)

    // zero own slice of h buffer 0 (layout [b][j])
    #pragma unroll
    for (int q = 0; q < 4; q++)
        g_hbuf[0][myb * HIDDEN + j0 + jlb + q] = 0.f;

    float h_reg[4] = {0.f, 0.f, 0.f, 0.f};
    float c_reg[4] = {0.f, 0.f, 0.f, 0.f};

    // GEMM mapping: tile 64(b) x 32(c); thread = 4b x 4c
    const int tx  = tid & 7;
    const int ty  = tid >> 3;            // 0..15
    const int tx4 = tx * 4;
    const int ty4 = ty * 4;
    const int s_h = (ty & 7) << 2;       // ((m>>2)&7)<<2 for my 4 rows
    const int s_r = tx << 2;             // ((c>>2)&7)<<2 for my 4 cols
    const int xz_col = (tx4 >> 3) * HIDDEN + j0 + (tx4 & 7);

    grid_barrier();   // h_buf[0] fully zeroed everywhere

    int p = 0;
    for (int t = 0; t < SEQLEN; t++) {
        const float* hb  = g_hbuf[p];
        const float* xzt = g_xz + (size_t)t * (BATCH * GDIM);

        unsigned long long acc[4][4];
        #pragma unroll
        for (int i = 0; i < 4; i++)
            #pragma unroll
            for (int j = 0; j < 4; j++) acc[i][j] = 0ull;

        for (int kt = 0; kt < 8; kt++) {
            // h tile: [64 b][128 k], k-contiguous rows, swizzled; .cv bypass L1
            #pragma unroll
            for (int r = 0; r < 16; r++) {
                int li = r * P2T + tid;
                int b  = li >> 5;
                int c4 = (li & 31) * 4;
                float4 v = __ldcv((const float4*)&hb[(size_t)b * HIDDEN + kt * 128 + c4]);
                *(float4*)&h_s[b * 128 + (c4 ^ (((b >> 2) & 7) << 2))] = v;
            }
            __syncthreads();

            const float* Rp = R_s + kt * 128;   // + c*1024 per column
            #pragma unroll 4
            for (int kk = 0; kk < 128; kk += 4) {
                int kh = kk ^ s_h;
                int kr = kk ^ s_r;
                ulonglong2 hv[4], rv[4];
                #pragma unroll
                for (int r = 0; r < 4; r++)
                    hv[r] = *(const ulonglong2*)&h_s[(ty4 + r) * 128 + kh];
                #pragma unroll
                for (int q = 0; q < 4; q++)
                    rv[q] = *(const ulonglong2*)&Rp[(tx4 + q) * 1024 + kr];
                #pragma unroll
                for (int r = 0; r < 4; r++)
                    #pragma unroll
                    for (int q = 0; q < 4; q++) {
                        ffma2(acc[r][q], hv[r].x, rv[q].x);
                        ffma2(acc[r][q], hv[r].y, rv[q].y);
                    }
            }
            __syncthreads();
        }

        // park z = xz + h@R in smem for the (b,j)-major gate phase
        #pragma unroll
        for (int i = 0; i < 4; i++) {
            float4 xzv = *(const float4*)&xzt[(size_t)(ty4 + i) * GDIM + xz_col];
            float4 zv;
            zv.x = usum(acc[i][0]) + xzv.x;
            zv.y = usum(acc[i][1]) + xzv.y;
            zv.z = usum(acc[i][2]) + xzv.z;
            zv.w = usum(acc[i][3]) + xzv.w;
            *(float4*)&z_s[(ty4 + i) * 36 + tx4] = zv;
        }
        __syncthreads();

        // gate phase: this thread owns (b = myb, j = j0+jlb..+3)
        bool msk = (seq[myb * SEQLEN + t] != 0);
        const float* zb = z_s + myb * 36;
        #pragma unroll
        for (int q = 0; q < 4; q++) {
            int jl = jlb + q;
            float zi = zb[jl];
            float zf = zb[8  + jl];
            float zg = zb[16 + jl];
            float zo = zb[24 + jl];
            float ig = 1.f / (1.f + expf(-zi));
            float fg = 1.f / (1.f + expf(-zf));
            float gg = tanhf(zg);
            float og = 1.f / (1.f + expf(-zo));
            float cn = fg * c_reg[q] + ig * gg;
            float hn = og * tanhf(cn);
            if (msk) { c_reg[q] = cn; h_reg[q] = hn; }
        }
        float* hbn = g_hbuf[p ^ 1];
        #pragma unroll
        for (int q = 0; q < 4; q++)
            hbn[myb * HIDDEN + j0 + jlb + q] = h_reg[q];

        p ^= 1;
        grid_barrier();
    }

    // final h -> d_out [b][1024]
    *(float4*)&out[myb * HIDDEN + j0 + jlb] =
        make_float4(h_reg[0], h_reg[1], h_reg[2], h_reg[3]);
}

// ---------------- launch ----------------
extern "C" void kernel_launch(void* const* d_in, const int* in_sizes, int n_in,
                              void* d_out, int out_size) {
    const float* emb  = nullptr;
    const float* W    = nullptr;
    const float* Rm   = nullptr;
    const float* bias = nullptr;
    const int*   seq  = nullptr;
    for (int i = 0; i < n_in; i++) {
        switch (in_sizes[i]) {
            case VOCAB * EMBED:     emb  = (const float*)d_in[i]; break;
            case EMBED * GDIM:      W    = (const float*)d_in[i]; break;
            case HIDDEN * GDIM:     Rm   = (const float*)d_in[i]; break;
            case GDIM:              bias = (const float*)d_in[i]; break;
            case BATCH * SEQLEN:    seq  = (const int*)d_in[i];   break;
        }
    }
    (void)out_size;

    const int smem2 = (32 * 1024 + 64 * 128 + 64 * 36) * (int)sizeof(float); // 173,056 B
    cudaFuncSetAttribute(lstm_kernel, cudaFuncAttributeMaxDynamicSharedMemorySize, smem2);

    dim3 g1(GDIM / 64, (SEQLEN * BATCH) / 64);   // (64, 512)
    xz_gemm_kernel<<<g1, 256>>>(emb, W, bias, seq);
    lstm_kernel<<<NCTA, P2T, smem2>>>(Rm, seq, (float*)d_out);
}

// round 7
// speedup vs baseline: 1.1955x; 1.1955x over previous
#include <cuda_runtime.h>
#include <cuda_bf16.h>
#include <math.h>
#include <stdint.h>

#define VOCAB   32000
#define EMBED   300
#define HIDDEN  1024
#define BATCH   64
#define SEQLEN  512
#define GDIM    4096

#define NCTA2   128    // persistent CTAs for LSTM (all resident, 1/SM)
#define TPB2    128

// ---------------- device scratch ----------------
__device__ float          g_xz[(size_t)SEQLEN * BATCH * GDIM];        // [t][b][g]
__device__ __nv_bfloat16  g_hsplit[2][2 * 64 * 1024];                 // [buf][plane hi/lo][b*1024+k]
__device__ __nv_bfloat16  g_Rsplit[(size_t)NCTA2 * 32 * 2048];        // [cta][n][k] k<1024:Rhi else Rlo
__device__ unsigned       g_bar_count;
__device__ volatile unsigned g_bar_gen;

// ---------------- grid barrier (all NCTA2 CTAs resident) -----------------
__device__ __forceinline__ void grid_barrier() {
    __syncthreads();
    if (threadIdx.x == 0) {
        __threadfence();
        unsigned g = g_bar_gen;
        if (atomicAdd(&g_bar_count, 1u) == NCTA2 - 1u) {
            atomicExch(&g_bar_count, 0u);
            __threadfence();
            g_bar_gen = g + 1u;
        } else {
            while (g_bar_gen == g) { __nanosleep(32); }
        }
        __threadfence();
    }
    __syncthreads();
}

// bf16 mma.sync m16n8k16, fp32 accumulate (sm_80+ baseline feature)
__device__ __forceinline__ void mma16816(float* d,
                                         uint32_t a0, uint32_t a1, uint32_t a2, uint32_t a3,
                                         uint32_t b0, uint32_t b1) {
    asm volatile("mma.sync.aligned.m16n8k16.row.col.f32.bf16.bf16.f32 "
        "{%0,%1,%2,%3}, {%4,%5,%6,%7}, {%8,%9}, {%0,%1,%2,%3};"
        : "+f"(d[0]), "+f"(d[1]), "+f"(d[2]), "+f"(d[3])
        : "r"(a0), "r"(a1), "r"(a2), "r"(a3), "r"(b0), "r"(b1));
}

// =========================================================================
// Prologue: zero h-split buffers
// =========================================================================
__global__ void hinit_kernel() {
    uint4 z = make_uint4(0, 0, 0, 0);
    int n4 = 2 * 2 * 64 * 1024 / 8;
    for (int i = blockIdx.x * blockDim.x + threadIdx.x; i < n4; i += gridDim.x * blockDim.x)
        ((uint4*)g_hsplit)[i] = z;
}

// =========================================================================
// Prologue: split R into bf16 hi/lo, CTA-grouped [cta][n][k]
// n = gate*8 + jl  ->  global col = gate*1024 + cta*8 + jl
// k<1024: hi(R[k][col]) ; k>=1024: lo(R[k-1024][col])
// =========================================================================
__global__ void rsplit_kernel(const float* __restrict__ Rm) {
    size_t i = (size_t)blockIdx.x * blockDim.x + threadIdx.x;
    if (i >= (size_t)NCTA2 * 32 * 2048) return;
    int k   = (int)(i & 2047);
    int n   = (int)((i >> 11) & 31);
    int cta = (int)(i >> 16);
    int col = (n >> 3) * 1024 + cta * 8 + (n & 7);
    int ks  = k & 1023;
    float x = Rm[(size_t)ks * GDIM + col];
    __nv_bfloat16 hi = __float2bfloat16(x);
    g_Rsplit[i] = (k < 1024) ? hi : __float2bfloat16(x - __bfloat162float(hi));
}

// =========================================================================
// Phase 1: xz = emb[seq] @ W + bias   (SIMT fp32, known-good)
// =========================================================================
__global__ void __launch_bounds__(256) xz_gemm_kernel(
    const float* __restrict__ emb, const float* __restrict__ W,
    const float* __restrict__ bias, const int* __restrict__ seq)
{
    __shared__ float As[32][64];
    __shared__ float Bs[32][64];
    __shared__ int   toks[64];

    const int tid = threadIdx.x;
    const int m0  = blockIdx.y * 64;
    const int n0  = blockIdx.x * 64;

    if (tid < 64) {
        int m = m0 + tid;
        toks[tid] = seq[(m & 63) * SEQLEN + (m >> 6)];
    }
    __syncthreads();

    const int tx4 = (tid & 15) * 4;
    const int ty4 = (tid >> 4) * 4;

    float acc[4][4];
    {
        float4 bv = *(const float4*)&bias[n0 + tx4];
        #pragma unroll
        for (int i = 0; i < 4; i++) {
            acc[i][0] = bv.x; acc[i][1] = bv.y; acc[i][2] = bv.z; acc[i][3] = bv.w;
        }
    }

    for (int k0 = 0; k0 < EMBED; k0 += 32) {
        #pragma unroll
        for (int pass = 0; pass < 2; pass++) {
            int r  = (tid >> 3) + pass * 32;
            int cc = (tid & 7) * 4;
            int kk = k0 + cc;
            float4 v = make_float4(0.f, 0.f, 0.f, 0.f);
            if (kk < EMBED)
                v = *(const float4*)&emb[(size_t)toks[r] * EMBED + kk];
            As[cc + 0][r] = v.x; As[cc + 1][r] = v.y;
            As[cc + 2][r] = v.z; As[cc + 3][r] = v.w;
        }
        #pragma unroll
        for (int pass = 0; pass < 2; pass++) {
            int r  = (tid >> 4) + pass * 16;
            int e  = k0 + r;
            int cc = (tid & 15) * 4;
            float4 v = make_float4(0.f, 0.f, 0.f, 0.f);
            if (e < EMBED)
                v = *(const float4*)&W[(size_t)e * GDIM + n0 + cc];
            *(float4*)&Bs[r][cc] = v;
        }
        __syncthreads();

        #pragma unroll
        for (int kk = 0; kk < 32; kk++) {
            float4 a = *(const float4*)&As[kk][ty4];
            float4 b = *(const float4*)&Bs[kk][tx4];
            acc[0][0] += a.x*b.x; acc[0][1] += a.x*b.y; acc[0][2] += a.x*b.z; acc[0][3] += a.x*b.w;
            acc[1][0] += a.y*b.x; acc[1][1] += a.y*b.y; acc[1][2] += a.y*b.z; acc[1][3] += a.y*b.w;
            acc[2][0] += a.z*b.x; acc[2][1] += a.z*b.y; acc[2][2] += a.z*b.z; acc[2][3] += a.z*b.w;
            acc[3][0] += a.w*b.x; acc[3][1] += a.w*b.y; acc[3][2] += a.w*b.z; acc[3][3] += a.w*b.w;
        }
        __syncthreads();
    }

    #pragma unroll
    for (int i = 0; i < 4; i++) {
        float4 v = make_float4(acc[i][0], acc[i][1], acc[i][2], acc[i][3]);
        *(float4*)&g_xz[(size_t)(m0 + ty4 + i) * GDIM + n0 + tx4] = v;
    }
}

// =========================================================================
// Phase 2: persistent LSTM scan on mma.sync (HMMA bf16, fp32 acc).
// CTA owns 32 z-cols (8 j x 4 gates). B = [Rhi|Rlo] [32n][2048k] resident
// in smem. A = h hi/lo planes streamed in 64-k chunks, reg double-buffer.
// z = hi@Rhi + hi@Rlo + lo@Rhi  (3-term bf16 split, ~2^-17 error).
// =========================================================================
// smem layout (bytes)
#define SM_B    0          // 32 rows x 2056 halves (pad 8)  = 131,584
#define BSTR    2056       // halves
#define SM_A    131584     // 2 bufs x 64 rows x 72 halves   = 18,432
#define ASTR    72         // halves
#define SM_Z    150016     // 64 x 33 floats                 = 8,448
#define ZSTR    33
#define SMEM2   158464

__global__ void __launch_bounds__(TPB2, 1)
lstm_mma_kernel(const int* __restrict__ seq, float* __restrict__ out)
{
    extern __shared__ char smem[];
    __nv_bfloat16* B_s = (__nv_bfloat16*)(smem + SM_B);
    float*         z_s = (float*)(smem + SM_Z);

    const int tid  = threadIdx.x;
    const int wid  = tid >> 5;
    const int lane = tid & 31;
    const int cta  = blockIdx.x;
    const int m0   = wid * 16;           // warp's 16 batch rows
    const int fg   = lane >> 2;          // fragment group row/col
    const int ft   = lane & 3;           // fragment thread-in-group

    // ---- load resident B slice (32 x 2048 halves) ----
    {
        const uint4* src = (const uint4*)(g_Rsplit + (size_t)cta * 32 * 2048);
        for (int idx = tid; idx < 32 * 256; idx += TPB2) {
            int r = idx >> 8, c = idx & 255;
            *(uint4*)(smem + SM_B + r * (BSTR * 2) + c * 16) = src[r * 256 + c];
        }
    }

    // gate-phase ownership: b = tid>>1, jl0 = (tid&1)*4
    const int tb  = tid >> 1;
    const int jl0 = (tid & 1) * 4;
    float c_r[4] = {0.f, 0.f, 0.f, 0.f};
    float h_r[4] = {0.f, 0.f, 0.f, 0.f};

    grid_barrier();   // B_s loaded; h buffers zeroed by hinit

    int p = 0;
    for (int t = 0; t < SEQLEN; t++) {
        const __nv_bfloat16* hbase = g_hsplit[p];

        float acc[16];
        #pragma unroll
        for (int i = 0; i < 16; i++) acc[i] = 0.f;

        // chunk ci: ci<16 -> plane hi, k0=ci*64 (used vs Rhi AND Rlo)
        //           ci>=16 -> plane lo, k0=(ci-16)*64 (vs Rhi only)
        uint4 pf[4];
        {   // prefetch chunk 0
            const __nv_bfloat16* pl = hbase;   // hi plane, k0 = 0
            #pragma unroll
            for (int ii = 0; ii < 4; ii++) {
                int idx = ii * TPB2 + tid;
                int r = idx >> 3, c8 = idx & 7;
                pf[ii] = __ldcg((const uint4*)(pl + (size_t)r * 1024 + c8 * 8));
            }
        }
        {   // store chunk 0 -> buf 0
            #pragma unroll
            for (int ii = 0; ii < 4; ii++) {
                int idx = ii * TPB2 + tid;
                int r = idx >> 3, c8 = idx & 7;
                *(uint4*)(smem + SM_A + r * (ASTR * 2) + c8 * 16) = pf[ii];
            }
        }
        __syncthreads();

        for (int ci = 0; ci < 32; ci++) {
            // prefetch next chunk
            if (ci < 31) {
                int cn = ci + 1;
                const __nv_bfloat16* pl = hbase + (cn < 16 ? 0 : 65536);
                int k0n = (cn & 15) * 64;
                #pragma unroll
                for (int ii = 0; ii < 4; ii++) {
                    int idx = ii * TPB2 + tid;
                    int r = idx >> 3, c8 = idx & 7;
                    pf[ii] = __ldcg((const uint4*)(pl + (size_t)r * 1024 + k0n + c8 * 8));
                }
            }

            // MMA on current buffer
            {
                const __nv_bfloat16* Ab = (const __nv_bfloat16*)(smem + SM_A + (ci & 1) * 9216);
                const int k0   = (ci & 15) * 64;
                const int npass = (ci < 16) ? 2 : 1;
                #pragma unroll
                for (int pass = 0; pass < 2; pass++) {
                    if (pass < npass) {
                        const int kb = (ci < 16 && pass == 1) ? (1024 + k0) : k0;
                        #pragma unroll
                        for (int ks = 0; ks < 4; ks++) {
                            const int kl = ks * 16;
                            uint32_t a0 = *(const uint32_t*)&Ab[(m0 + fg)     * ASTR + kl + 2 * ft];
                            uint32_t a1 = *(const uint32_t*)&Ab[(m0 + fg + 8) * ASTR + kl + 2 * ft];
                            uint32_t a2 = *(const uint32_t*)&Ab[(m0 + fg)     * ASTR + kl + 2 * ft + 8];
                            uint32_t a3 = *(const uint32_t*)&Ab[(m0 + fg + 8) * ASTR + kl + 2 * ft + 8];
                            #pragma unroll
                            for (int q = 0; q < 4; q++) {
                                uint32_t b0 = *(const uint32_t*)&B_s[(q * 8 + fg) * BSTR + kb + kl + 2 * ft];
                                uint32_t b1 = *(const uint32_t*)&B_s[(q * 8 + fg) * BSTR + kb + kl + 2 * ft + 8];
                                mma16816(acc + q * 4, a0, a1, a2, a3, b0, b1);
                            }
                        }
                    }
                }
            }

            // stage next chunk into the other buffer
            if (ci < 31) {
                #pragma unroll
                for (int ii = 0; ii < 4; ii++) {
                    int idx = ii * TPB2 + tid;
                    int r = idx >> 3, c8 = idx & 7;
                    *(uint4*)(smem + SM_A + ((ci + 1) & 1) * 9216 + r * (ASTR * 2) + c8 * 16) = pf[ii];
                }
            }
            __syncthreads();
        }

        // ---- park z tile in smem ----
        #pragma unroll
        for (int q = 0; q < 4; q++) {
            z_s[(m0 + fg)     * ZSTR + q * 8 + 2 * ft]     = acc[q * 4 + 0];
            z_s[(m0 + fg)     * ZSTR + q * 8 + 2 * ft + 1] = acc[q * 4 + 1];
            z_s[(m0 + fg + 8) * ZSTR + q * 8 + 2 * ft]     = acc[q * 4 + 2];
            z_s[(m0 + fg + 8) * ZSTR + q * 8 + 2 * ft + 1] = acc[q * 4 + 3];
        }
        __syncthreads();

        // ---- gates: thread owns (b=tb, j = cta*8 + jl0..+3) ----
        {
            const float* xzr = g_xz + (size_t)t * (BATCH * GDIM) + (size_t)tb * GDIM + cta * 8;
            const bool msk = (seq[tb * SEQLEN + t] != 0);
            const float* zr = z_s + tb * ZSTR;
            float4 xi = *(const float4*)&xzr[jl0];
            float4 xf = *(const float4*)&xzr[1024 + jl0];
            float4 xg = *(const float4*)&xzr[2048 + jl0];
            float4 xo = *(const float4*)&xzr[3072 + jl0];
            const float* xip = &xi.x; const float* xfp = &xf.x;
            const float* xgp = &xg.x; const float* xop = &xo.x;
            #pragma unroll
            for (int q = 0; q < 4; q++) {
                int jl = jl0 + q;
                float zi = zr[jl]      + xip[q];
                float zf = zr[8 + jl]  + xfp[q];
                float zg = zr[16 + jl] + xgp[q];
                float zo = zr[24 + jl] + xop[q];
                float ig = 1.f / (1.f + expf(-zi));
                float fgt = 1.f / (1.f + expf(-zf));
                float gg = tanhf(zg);
                float og = 1.f / (1.f + expf(-zo));
                float cn = fgt * c_r[q] + ig * gg;
                float hn = og * tanhf(cn);
                if (msk) { c_r[q] = cn; h_r[q] = hn; }
            }
            // write split h for next step (4 hi + 4 lo halves, 8B each)
            union { __nv_bfloat16 b[4]; uint2 u; } hiP, loP;
            #pragma unroll
            for (int q = 0; q < 4; q++) {
                __nv_bfloat16 hi = __float2bfloat16(h_r[q]);
                hiP.b[q] = hi;
                loP.b[q] = __float2bfloat16(h_r[q] - __bfloat162float(hi));
            }
            __nv_bfloat16* hN = g_hsplit[p ^ 1];
            *(uint2*)&hN[(size_t)tb * 1024 + cta * 8 + jl0]         = hiP.u;
            *(uint2*)&hN[65536 + (size_t)tb * 1024 + cta * 8 + jl0] = loP.u;
        }

        p ^= 1;
        grid_barrier();
    }

    // final h -> out[b][1024]
    *(float4*)&out[(size_t)tb * HIDDEN + cta * 8 + jl0] =
        make_float4(h_r[0], h_r[1], h_r[2], h_r[3]);
}

// ---------------- launch ----------------
extern "C" void kernel_launch(void* const* d_in, const int* in_sizes, int n_in,
                              void* d_out, int out_size) {
    const float* emb  = nullptr;
    const float* W    = nullptr;
    const float* Rm   = nullptr;
    const float* bias = nullptr;
    const int*   seq  = nullptr;
    for (int i = 0; i < n_in; i++) {
        switch (in_sizes[i]) {
            case VOCAB * EMBED:  emb  = (const float*)d_in[i]; break;
            case EMBED * GDIM:   W    = (const float*)d_in[i]; break;
            case HIDDEN * GDIM:  Rm   = (const float*)d_in[i]; break;
            case GDIM:           bias = (const float*)d_in[i]; break;
            case BATCH * SEQLEN: seq  = (const int*)d_in[i];   break;
        }
    }
    (void)out_size;

    cudaFuncSetAttribute(lstm_mma_kernel, cudaFuncAttributeMaxDynamicSharedMemorySize, SMEM2);

    hinit_kernel<<<64, 256>>>();
    rsplit_kernel<<<(int)(((size_t)NCTA2 * 32 * 2048 + 255) / 256), 256>>>(Rm);
    dim3 g1(GDIM / 64, (SEQLEN * BATCH) / 64);
    xz_gemm_kernel<<<g1, 256>>>(emb, W, bias, seq);
    lstm_mma_kernel<<<NCTA2, TPB2, SMEM2>>>(seq, (float*)d_out);
}

// round 8
// speedup vs baseline: 1.4926x; 1.2485x over previous
#include <cuda_runtime.h>
#include <cuda_bf16.h>
#include <math.h>
#include <stdint.h>

#define VOCAB   32000
#define EMBED   300
#define HIDDEN  1024
#define BATCH   64
#define SEQLEN  512
#define GDIM    4096

#define NCTA2   128    // persistent CTAs for LSTM (all resident, 1/SM)
#define TPB2    256

// ---------------- device scratch ----------------
__device__ float          g_xz[(size_t)SEQLEN * BATCH * GDIM];        // [t][b][g]
__device__ __nv_bfloat16  g_hsplit[2][2 * 64 * 1024];                 // [buf][plane hi/lo][b*1024+k]
__device__ __nv_bfloat16  g_Rsplit[(size_t)NCTA2 * 32 * 2048];        // [cta][n][k] k<1024:Rhi else Rlo
__device__ unsigned       g_bar_count;
__device__ volatile unsigned g_bar_gen;

// ---------------- grid barrier (all NCTA2 CTAs resident) -----------------
__device__ __forceinline__ void grid_barrier() {
    __syncthreads();
    if (threadIdx.x == 0) {
        __threadfence();
        unsigned g = g_bar_gen;
        if (atomicAdd(&g_bar_count, 1u) == NCTA2 - 1u) {
            atomicExch(&g_bar_count, 0u);
            __threadfence();
            g_bar_gen = g + 1u;
        } else {
            while (g_bar_gen == g) { __nanosleep(32); }
        }
        __threadfence();
    }
    __syncthreads();
}

// bf16 mma.sync m16n8k16, fp32 accumulate
__device__ __forceinline__ void mma16816(float* d,
                                         uint32_t a0, uint32_t a1, uint32_t a2, uint32_t a3,
                                         uint32_t b0, uint32_t b1) {
    asm volatile("mma.sync.aligned.m16n8k16.row.col.f32.bf16.bf16.f32 "
        "{%0,%1,%2,%3}, {%4,%5,%6,%7}, {%8,%9}, {%0,%1,%2,%3};"
        : "+f"(d[0]), "+f"(d[1]), "+f"(d[2]), "+f"(d[3])
        : "r"(a0), "r"(a1), "r"(a2), "r"(a3), "r"(b0), "r"(b1));
}
__device__ __forceinline__ void ldsm4(uint32_t& r0, uint32_t& r1, uint32_t& r2, uint32_t& r3,
                                      uint32_t addr) {
    asm volatile("ldmatrix.sync.aligned.m8n8.x4.shared.b16 {%0,%1,%2,%3}, [%4];"
        : "=r"(r0), "=r"(r1), "=r"(r2), "=r"(r3) : "r"(addr));
}
__device__ __forceinline__ void cp16(uint32_t dst, const void* src) {
    asm volatile("cp.async.cg.shared.global [%0], [%1], 16;" :: "r"(dst), "l"(src));
}
#define CP_COMMIT() asm volatile("cp.async.commit_group;" ::: "memory")
#define CP_WAIT0()  asm volatile("cp.async.wait_group 0;" ::: "memory")

__device__ __forceinline__ uint32_t smem_to_u32(const void* p) {
    uint32_t a;
    asm("{ .reg .u64 t; cvta.to.shared.u64 t, %1; cvt.u32.u64 %0, t; }" : "=r"(a) : "l"(p));
    return a;
}

// =========================================================================
// Prologue: zero h-split buffers
// =========================================================================
__global__ void hinit_kernel() {
    uint4 z = make_uint4(0, 0, 0, 0);
    int n4 = 2 * 2 * 64 * 1024 / 8;
    for (int i = blockIdx.x * blockDim.x + threadIdx.x; i < n4; i += gridDim.x * blockDim.x)
        ((uint4*)g_hsplit)[i] = z;
}

// =========================================================================
// Prologue: split R into bf16 hi/lo, CTA-grouped [cta][n][k]
// n = gate*8 + jl -> global col = gate*1024 + cta*8 + jl
// =========================================================================
__global__ void rsplit_kernel(const float* __restrict__ Rm) {
    size_t i = (size_t)blockIdx.x * blockDim.x + threadIdx.x;
    if (i >= (size_t)NCTA2 * 32 * 2048) return;
    int k   = (int)(i & 2047);
    int n   = (int)((i >> 11) & 31);
    int cta = (int)(i >> 16);
    int col = (n >> 3) * 1024 + cta * 8 + (n & 7);
    int ks  = k & 1023;
    float x = Rm[(size_t)ks * GDIM + col];
    __nv_bfloat16 hi = __float2bfloat16(x);
    g_Rsplit[i] = (k < 1024) ? hi : __float2bfloat16(x - __bfloat162float(hi));
}

// =========================================================================
// Phase 1: xz = emb[seq] @ W + bias   (SIMT fp32, known-good)
// =========================================================================
__global__ void __launch_bounds__(256) xz_gemm_kernel(
    const float* __restrict__ emb, const float* __restrict__ W,
    const float* __restrict__ bias, const int* __restrict__ seq)
{
    __shared__ float As[32][64];
    __shared__ float Bs[32][64];
    __shared__ int   toks[64];

    const int tid = threadIdx.x;
    const int m0  = blockIdx.y * 64;
    const int n0  = blockIdx.x * 64;

    if (tid < 64) {
        int m = m0 + tid;
        toks[tid] = seq[(m & 63) * SEQLEN + (m >> 6)];
    }
    __syncthreads();

    const int tx4 = (tid & 15) * 4;
    const int ty4 = (tid >> 4) * 4;

    float acc[4][4];
    {
        float4 bv = *(const float4*)&bias[n0 + tx4];
        #pragma unroll
        for (int i = 0; i < 4; i++) {
            acc[i][0] = bv.x; acc[i][1] = bv.y; acc[i][2] = bv.z; acc[i][3] = bv.w;
        }
    }

    for (int k0 = 0; k0 < EMBED; k0 += 32) {
        #pragma unroll
        for (int pass = 0; pass < 2; pass++) {
            int r  = (tid >> 3) + pass * 32;
            int cc = (tid & 7) * 4;
            int kk = k0 + cc;
            float4 v = make_float4(0.f, 0.f, 0.f, 0.f);
            if (kk < EMBED)
                v = *(const float4*)&emb[(size_t)toks[r] * EMBED + kk];
            As[cc + 0][r] = v.x; As[cc + 1][r] = v.y;
            As[cc + 2][r] = v.z; As[cc + 3][r] = v.w;
        }
        #pragma unroll
        for (int pass = 0; pass < 2; pass++) {
            int r  = (tid >> 4) + pass * 16;
            int e  = k0 + r;
            int cc = (tid & 15) * 4;
            float4 v = make_float4(0.f, 0.f, 0.f, 0.f);
            if (e < EMBED)
                v = *(const float4*)&W[(size_t)e * GDIM + n0 + cc];
            *(float4*)&Bs[r][cc] = v;
        }
        __syncthreads();

        #pragma unroll
        for (int kk = 0; kk < 32; kk++) {
            float4 a = *(const float4*)&As[kk][ty4];
            float4 b = *(const float4*)&Bs[kk][tx4];
            acc[0][0] += a.x*b.x; acc[0][1] += a.x*b.y; acc[0][2] += a.x*b.z; acc[0][3] += a.x*b.w;
            acc[1][0] += a.y*b.x; acc[1][1] += a.y*b.y; acc[1][2] += a.y*b.z; acc[1][3] += a.y*b.w;
            acc[2][0] += a.z*b.x; acc[2][1] += a.z*b.y; acc[2][2] += a.z*b.z; acc[2][3] += a.z*b.w;
            acc[3][0] += a.w*b.x; acc[3][1] += a.w*b.y; acc[3][2] += a.w*b.z; acc[3][3] += a.w*b.w;
        }
        __syncthreads();
    }

    #pragma unroll
    for (int i = 0; i < 4; i++) {
        float4 v = make_float4(acc[i][0], acc[i][1], acc[i][2], acc[i][3]);
        *(float4*)&g_xz[(size_t)(m0 + ty4 + i) * GDIM + n0 + tx4] = v;
    }
}

// =========================================================================
// Phase 2 v2: 256 threads, k=256 chunks, cp.async staging, ldmatrix frags.
// Warp w: m16 tile (w&3)*16, n16 tile (w>>2)*16.
// Chunks 0-3: hi plane k0=ci*256, used vs Rhi AND Rlo; 4-7: lo plane vs Rhi.
// =========================================================================
// smem layout (bytes)
#define SM_B     0         // 32 rows x 4112 B           = 131,584
#define BSTR_B   4112      // 2056 halves (pad 8)
#define SM_A     131584    // 2 bufs x 64 rows x 528 B   = 67,584
#define ABUF     33792
#define ASTR_B   528       // 264 halves (pad 8)
#define SM_Z     199168    // 64 x 33 floats             = 8,448
#define SMEM2    207616

__global__ void __launch_bounds__(TPB2, 1)
lstm_mma_kernel(const int* __restrict__ seq, float* __restrict__ out)
{
    extern __shared__ char smem[];
    const uint32_t sb = smem_to_u32(smem);
    const int tid  = threadIdx.x;
    const int wid  = tid >> 5;
    const int lane = tid & 31;
    const int cta  = blockIdx.x;
    const int m0   = (wid & 3) * 16;
    const int nbase = (wid >> 2) * 16;

    // ---- load resident B slice (32 x 2048 halves) ----
    {
        const uint4* src = (const uint4*)(g_Rsplit + (size_t)cta * 32 * 2048);
        for (int idx = tid; idx < 32 * 256; idx += TPB2) {
            int r = idx >> 8, c = idx & 255;
            *(uint4*)(smem + SM_B + r * BSTR_B + c * 16) = src[r * 256 + c];
        }
    }

    // gate ownership: b = tid&63, 2 j-cols at gj
    const int gb = tid & 63;
    const int gj = (tid >> 6) * 2;
    float c_r[2] = {0.f, 0.f}, h_r[2] = {0.f, 0.f};

    // ldmatrix lane address components
    const int aRow = m0 + (lane & 7) + ((lane >> 3) & 1) * 8;
    const int aK8  = ((lane >> 4) & 1) * 8;
    const int bRow = nbase + (lane & 7) + ((lane >> 4) & 1) * 8;
    const int bK8  = ((lane >> 3) & 1) * 8;
    const uint32_t aAddr0 = sb + SM_A + aRow * ASTR_B + aK8 * 2;
    const uint32_t bAddr0 = sb + SM_B + bRow * BSTR_B + bK8 * 2;

    float* z_s = (float*)(smem + SM_Z);

    grid_barrier();   // B_s loaded everywhere; h buffers zeroed by hinit

    int p = 0;
    for (int t = 0; t < SEQLEN; t++) {
        const __nv_bfloat16* hbase = g_hsplit[p];

        float acc[8];
        #pragma unroll
        for (int i = 0; i < 8; i++) acc[i] = 0.f;

        // issue chunk 0 (hi plane, k0=0) -> buf 0
        #pragma unroll
        for (int i = 0; i < 8; i++) {
            int idx = i * TPB2 + tid;
            int r = idx >> 5, c = idx & 31;
            cp16(sb + SM_A + r * ASTR_B + c * 16, hbase + (size_t)r * 1024 + c * 8);
        }
        CP_COMMIT();

        for (int ci = 0; ci < 8; ci++) {
            CP_WAIT0();
            __syncthreads();
            if (ci < 7) {
                int cn = ci + 1;
                const __nv_bfloat16* pl = hbase + (cn < 4 ? 0 : 65536);
                int k0n = (cn & 3) * 256;
                #pragma unroll
                for (int i = 0; i < 8; i++) {
                    int idx = i * TPB2 + tid;
                    int r = idx >> 5, c = idx & 31;
                    cp16(sb + SM_A + (cn & 1) * ABUF + r * ASTR_B + c * 16,
                         pl + (size_t)r * 1024 + k0n + c * 8);
                }
                CP_COMMIT();
            }

            const uint32_t aB = aAddr0 + (ci & 1) * ABUF;
            const int k0 = (ci & 3) * 256;
            const bool isHi = (ci < 4);
            #pragma unroll
            for (int ks = 0; ks < 16; ks++) {
                const int kl = ks * 16;
                uint32_t a0, a1, a2, a3, b0, b1, b2, b3;
                ldsm4(a0, a1, a2, a3, aB + kl * 2);
                ldsm4(b0, b1, b2, b3, bAddr0 + (k0 + kl) * 2);
                mma16816(acc,     a0, a1, a2, a3, b0, b1);
                mma16816(acc + 4, a0, a1, a2, a3, b2, b3);
                if (isHi) {
                    ldsm4(b0, b1, b2, b3, bAddr0 + (1024 + k0 + kl) * 2);
                    mma16816(acc,     a0, a1, a2, a3, b0, b1);
                    mma16816(acc + 4, a0, a1, a2, a3, b2, b3);
                }
            }
        }

        // ---- park z tile in smem ----
        {
            const int fg = lane >> 2, ft = lane & 3;
            #pragma unroll
            for (int blk = 0; blk < 2; blk++) {
                int ncol = nbase + blk * 8 + 2 * ft;
                z_s[(m0 + fg)     * 33 + ncol]     = acc[blk * 4 + 0];
                z_s[(m0 + fg)     * 33 + ncol + 1] = acc[blk * 4 + 1];
                z_s[(m0 + fg + 8) * 33 + ncol]     = acc[blk * 4 + 2];
                z_s[(m0 + fg + 8) * 33 + ncol + 1] = acc[blk * 4 + 3];
            }
        }
        __syncthreads();

        // ---- gates: thread owns (b=gb, j = cta*8 + gj..+1) ----
        {
            const float* xzr = g_xz + (size_t)t * (BATCH * GDIM) + (size_t)gb * GDIM + cta * 8 + gj;
            const bool msk = (seq[gb * SEQLEN + t] != 0);
            const float* zr = z_s + gb * 33;
            #pragma unroll
            for (int q = 0; q < 2; q++) {
                int jl = gj + q;
                float zi = zr[jl]      + xzr[q];
                float zf = zr[8 + jl]  + xzr[1024 + q];
                float zg = zr[16 + jl] + xzr[2048 + q];
                float zo = zr[24 + jl] + xzr[3072 + q];
                float ig  = 1.f / (1.f + expf(-zi));
                float fgt = 1.f / (1.f + expf(-zf));
                float gg  = tanhf(zg);
                float og  = 1.f / (1.f + expf(-zo));
                float cn = fgt * c_r[q] + ig * gg;
                float hn = og * tanhf(cn);
                if (msk) { c_r[q] = cn; h_r[q] = hn; }
            }
            union { __nv_bfloat16 b[2]; uint32_t u; } hiP, loP;
            #pragma unroll
            for (int q = 0; q < 2; q++) {
                __nv_bfloat16 hi = __float2bfloat16(h_r[q]);
                hiP.b[q] = hi;
                loP.b[q] = __float2bfloat16(h_r[q] - __bfloat162float(hi));
            }
            __nv_bfloat16* hN = g_hsplit[p ^ 1];
            *(uint32_t*)&hN[(size_t)gb * 1024 + cta * 8 + gj]         = hiP.u;
            *(uint32_t*)&hN[65536 + (size_t)gb * 1024 + cta * 8 + gj] = loP.u;
        }

        p ^= 1;
        grid_barrier();
    }

    // final h -> out[b][1024]
    *(float2*)&out[(size_t)gb * HIDDEN + cta * 8 + gj] = make_float2(h_r[0], h_r[1]);
}

// ---------------- launch ----------------
extern "C" void kernel_launch(void* const* d_in, const int* in_sizes, int n_in,
                              void* d_out, int out_size) {
    const float* emb  = nullptr;
    const float* W    = nullptr;
    const float* Rm   = nullptr;
    const float* bias = nullptr;
    const int*   seq  = nullptr;
    for (int i = 0; i < n_in; i++) {
        switch (in_sizes[i]) {
            case VOCAB * EMBED:  emb  = (const float*)d_in[i]; break;
            case EMBED * GDIM:   W    = (const float*)d_in[i]; break;
            case HIDDEN * GDIM:  Rm   = (const float*)d_in[i]; break;
            case GDIM:           bias = (const float*)d_in[i]; break;
            case BATCH * SEQLEN: seq  = (const int*)d_in[i];   break;
        }
    }
    (void)out_size;

    cudaFuncSetAttribute(lstm_mma_kernel, cudaFuncAttributeMaxDynamicSharedMemorySize, SMEM2);

    hinit_kernel<<<64, 256>>>();
    rsplit_kernel<<<(int)(((size_t)NCTA2 * 32 * 2048 + 255) / 256), 256>>>(Rm);
    dim3 g1(GDIM / 64, (SEQLEN * BATCH) / 64);
    xz_gemm_kernel<<<g1, 256>>>(emb, W, bias, seq);
    lstm_mma_kernel<<<NCTA2, TPB2, SMEM2>>>(seq, (float*)d_out);
}

// round 9
// speedup vs baseline: 1.4970x; 1.0029x over previous
#include <cuda_runtime.h>
#include <cuda_bf16.h>
#include <math.h>
#include <stdint.h>

#define VOCAB   32000
#define EMBED   300
#define HIDDEN  1024
#define BATCH   64
#define SEQLEN  512
#define GDIM    4096

#define NCTA2   128    // persistent CTAs for LSTM (all resident, 1/SM)
#define TPB2    256

// ---------------- device scratch ----------------
__device__ float          g_xz[(size_t)SEQLEN * BATCH * GDIM];        // [t][b][g]
__device__ __nv_bfloat16  g_hsplit[2][2 * 64 * 1024];                 // [buf][plane hi/lo][b*1024+k]
__device__ __nv_bfloat16  g_Rsplit[(size_t)NCTA2 * 32 * 2048];        // [cta][n][k] k<1024:Rhi else Rlo
__device__ unsigned       g_bar_count;
__device__ volatile unsigned g_bar_gen;

// ---------------- grid barrier (all NCTA2 CTAs resident) -----------------
__device__ __forceinline__ void grid_barrier() {
    __syncthreads();
    if (threadIdx.x == 0) {
        __threadfence();
        unsigned g = g_bar_gen;
        if (atomicAdd(&g_bar_count, 1u) == NCTA2 - 1u) {
            atomicExch(&g_bar_count, 0u);
            __threadfence();
            g_bar_gen = g + 1u;
        } else {
            while (g_bar_gen == g) { __nanosleep(32); }
        }
        __threadfence();
    }
    __syncthreads();
}

// bf16 mma.sync m16n8k16, fp32 accumulate
__device__ __forceinline__ void mma16816(float* d,
                                         uint32_t a0, uint32_t a1, uint32_t a2, uint32_t a3,
                                         uint32_t b0, uint32_t b1) {
    asm volatile("mma.sync.aligned.m16n8k16.row.col.f32.bf16.bf16.f32 "
        "{%0,%1,%2,%3}, {%4,%5,%6,%7}, {%8,%9}, {%0,%1,%2,%3};"
        : "+f"(d[0]), "+f"(d[1]), "+f"(d[2]), "+f"(d[3])
        : "r"(a0), "r"(a1), "r"(a2), "r"(a3), "r"(b0), "r"(b1));
}
__device__ __forceinline__ void ldsm4(uint32_t& r0, uint32_t& r1, uint32_t& r2, uint32_t& r3,
                                      uint32_t addr) {
    asm volatile("ldmatrix.sync.aligned.m8n8.x4.shared.b16 {%0,%1,%2,%3}, [%4];"
        : "=r"(r0), "=r"(r1), "=r"(r2), "=r"(r3) : "r"(addr));
}
__device__ __forceinline__ void cp16(uint32_t dst, const void* src) {
    asm volatile("cp.async.cg.shared.global [%0], [%1], 16;" :: "r"(dst), "l"(src));
}
#define CP_COMMIT() asm volatile("cp.async.commit_group;" ::: "memory")
#define CP_WAIT0()  asm volatile("cp.async.wait_group 0;" ::: "memory")

__device__ __forceinline__ uint32_t smem_to_u32(const void* p) {
    uint32_t a;
    asm("{ .reg .u64 t; cvta.to.shared.u64 t, %1; cvt.u32.u64 %0, t; }" : "=r"(a) : "l"(p));
    return a;
}

// =========================================================================
// Prologue: zero h-split buffers
// =========================================================================
__global__ void hinit_kernel() {
    uint4 z = make_uint4(0, 0, 0, 0);
    int n4 = 2 * 2 * 64 * 1024 / 8;
    for (int i = blockIdx.x * blockDim.x + threadIdx.x; i < n4; i += gridDim.x * blockDim.x)
        ((uint4*)g_hsplit)[i] = z;
}

// =========================================================================
// Prologue: split R into bf16 hi/lo, CTA-grouped [cta][n][k]
// n = gate*8 + jl -> global col = gate*1024 + cta*8 + jl
// =========================================================================
__global__ void rsplit_kernel(const float* __restrict__ Rm) {
    size_t i = (size_t)blockIdx.x * blockDim.x + threadIdx.x;
    if (i >= (size_t)NCTA2 * 32 * 2048) return;
    int k   = (int)(i & 2047);
    int n   = (int)((i >> 11) & 31);
    int cta = (int)(i >> 16);
    int col = (n >> 3) * 1024 + cta * 8 + (n & 7);
    int ks  = k & 1023;
    float x = Rm[(size_t)ks * GDIM + col];
    __nv_bfloat16 hi = __float2bfloat16(x);
    g_Rsplit[i] = (k < 1024) ? hi : __float2bfloat16(x - __bfloat162float(hi));
}

// =========================================================================
// Phase 1: xz = emb[seq] @ W + bias   (SIMT fp32, known-good)
// =========================================================================
__global__ void __launch_bounds__(256) xz_gemm_kernel(
    const float* __restrict__ emb, const float* __restrict__ W,
    const float* __restrict__ bias, const int* __restrict__ seq)
{
    __shared__ float As[32][64];
    __shared__ float Bs[32][64];
    __shared__ int   toks[64];

    const int tid = threadIdx.x;
    const int m0  = blockIdx.y * 64;
    const int n0  = blockIdx.x * 64;

    if (tid < 64) {
        int m = m0 + tid;
        toks[tid] = seq[(m & 63) * SEQLEN + (m >> 6)];
    }
    __syncthreads();

    const int tx4 = (tid & 15) * 4;
    const int ty4 = (tid >> 4) * 4;

    float acc[4][4];
    {
        float4 bv = *(const float4*)&bias[n0 + tx4];
        #pragma unroll
        for (int i = 0; i < 4; i++) {
            acc[i][0] = bv.x; acc[i][1] = bv.y; acc[i][2] = bv.z; acc[i][3] = bv.w;
        }
    }

    for (int k0 = 0; k0 < EMBED; k0 += 32) {
        #pragma unroll
        for (int pass = 0; pass < 2; pass++) {
            int r  = (tid >> 3) + pass * 32;
            int cc = (tid & 7) * 4;
            int kk = k0 + cc;
            float4 v = make_float4(0.f, 0.f, 0.f, 0.f);
            if (kk < EMBED)
                v = *(const float4*)&emb[(size_t)toks[r] * EMBED + kk];
            As[cc + 0][r] = v.x; As[cc + 1][r] = v.y;
            As[cc + 2][r] = v.z; As[cc + 3][r] = v.w;
        }
        #pragma unroll
        for (int pass = 0; pass < 2; pass++) {
            int r  = (tid >> 4) + pass * 16;
            int e  = k0 + r;
            int cc = (tid & 15) * 4;
            float4 v = make_float4(0.f, 0.f, 0.f, 0.f);
            if (e < EMBED)
                v = *(const float4*)&W[(size_t)e * GDIM + n0 + cc];
            *(float4*)&Bs[r][cc] = v;
        }
        __syncthreads();

        #pragma unroll
        for (int kk = 0; kk < 32; kk++) {
            float4 a = *(const float4*)&As[kk][ty4];
            float4 b = *(const float4*)&Bs[kk][tx4];
            acc[0][0] += a.x*b.x; acc[0][1] += a.x*b.y; acc[0][2] += a.x*b.z; acc[0][3] += a.x*b.w;
            acc[1][0] += a.y*b.x; acc[1][1] += a.y*b.y; acc[1][2] += a.y*b.z; acc[1][3] += a.y*b.w;
            acc[2][0] += a.z*b.x; acc[2][1] += a.z*b.y; acc[2][2] += a.z*b.z; acc[2][3] += a.z*b.w;
            acc[3][0] += a.w*b.x; acc[3][1] += a.w*b.y; acc[3][2] += a.w*b.z; acc[3][3] += a.w*b.w;
        }
        __syncthreads();
    }

    #pragma unroll
    for (int i = 0; i < 4; i++) {
        float4 v = make_float4(acc[i][0], acc[i][1], acc[i][2], acc[i][3]);
        *(float4*)&g_xz[(size_t)(m0 + ty4 + i) * GDIM + n0 + tx4] = v;
    }
}

// =========================================================================
// Phase 2 v2: 256 threads, k=256 chunks, cp.async staging, ldmatrix frags.
// Warp w: m16 tile (w&3)*16, n16 tile (w>>2)*16.
// Chunks 0-3: hi plane k0=ci*256, used vs Rhi AND Rlo; 4-7: lo plane vs Rhi.
// =========================================================================
// smem layout (bytes)
#define SM_B     0         // 32 rows x 4112 B           = 131,584
#define BSTR_B   4112      // 2056 halves (pad 8)
#define SM_A     131584    // 2 bufs x 64 rows x 528 B   = 67,584
#define ABUF     33792
#define ASTR_B   528       // 264 halves (pad 8)
#define SM_Z     199168    // 64 x 33 floats             = 8,448
#define SMEM2    207616

__global__ void __launch_bounds__(TPB2, 1)
lstm_mma_kernel(const int* __restrict__ seq, float* __restrict__ out)
{
    extern __shared__ char smem[];
    const uint32_t sb = smem_to_u32(smem);
    const int tid  = threadIdx.x;
    const int wid  = tid >> 5;
    const int lane = tid & 31;
    const int cta  = blockIdx.x;
    const int m0   = (wid & 3) * 16;
    const int nbase = (wid >> 2) * 16;

    // ---- load resident B slice (32 x 2048 halves) ----
    {
        const uint4* src = (const uint4*)(g_Rsplit + (size_t)cta * 32 * 2048);
        for (int idx = tid; idx < 32 * 256; idx += TPB2) {
            int r = idx >> 8, c = idx & 255;
            *(uint4*)(smem + SM_B + r * BSTR_B + c * 16) = src[r * 256 + c];
        }
    }

    // gate ownership: b = tid&63, 2 j-cols at gj
    const int gb = tid & 63;
    const int gj = (tid >> 6) * 2;
    float c_r[2] = {0.f, 0.f}, h_r[2] = {0.f, 0.f};

    // ldmatrix lane address components
    const int aRow = m0 + (lane & 7) + ((lane >> 3) & 1) * 8;
    const int aK8  = ((lane >> 4) & 1) * 8;
    const int bRow = nbase + (lane & 7) + ((lane >> 4) & 1) * 8;
    const int bK8  = ((lane >> 3) & 1) * 8;
    const uint32_t aAddr0 = sb + SM_A + aRow * ASTR_B + aK8 * 2;
    const uint32_t bAddr0 = sb + SM_B + bRow * BSTR_B + bK8 * 2;

    float* z_s = (float*)(smem + SM_Z);

    grid_barrier();   // B_s loaded everywhere; h buffers zeroed by hinit

    int p = 0;
    for (int t = 0; t < SEQLEN; t++) {
        const __nv_bfloat16* hbase = g_hsplit[p];

        float acc[8];
        #pragma unroll
        for (int i = 0; i < 8; i++) acc[i] = 0.f;

        // issue chunk 0 (hi plane, k0=0) -> buf 0
        #pragma unroll
        for (int i = 0; i < 8; i++) {
            int idx = i * TPB2 + tid;
            int r = idx >> 5, c = idx & 31;
            cp16(sb + SM_A + r * ASTR_B + c * 16, hbase + (size_t)r * 1024 + c * 8);
        }
        CP_COMMIT();

        for (int ci = 0; ci < 8; ci++) {
            CP_WAIT0();
            __syncthreads();
            if (ci < 7) {
                int cn = ci + 1;
                const __nv_bfloat16* pl = hbase + (cn < 4 ? 0 : 65536);
                int k0n = (cn & 3) * 256;
                #pragma unroll
                for (int i = 0; i < 8; i++) {
                    int idx = i * TPB2 + tid;
                    int r = idx >> 5, c = idx & 31;
                    cp16(sb + SM_A + (cn & 1) * ABUF + r * ASTR_B + c * 16,
                         pl + (size_t)r * 1024 + k0n + c * 8);
                }
                CP_COMMIT();
            }

            const uint32_t aB = aAddr0 + (ci & 1) * ABUF;
            const int k0 = (ci & 3) * 256;
            const bool isHi = (ci < 4);
            #pragma unroll
            for (int ks = 0; ks < 16; ks++) {
                const int kl = ks * 16;
                uint32_t a0, a1, a2, a3, b0, b1, b2, b3;
                ldsm4(a0, a1, a2, a3, aB + kl * 2);
                ldsm4(b0, b1, b2, b3, bAddr0 + (k0 + kl) * 2);
                mma16816(acc,     a0, a1, a2, a3, b0, b1);
                mma16816(acc + 4, a0, a1, a2, a3, b2, b3);
                if (isHi) {
                    ldsm4(b0, b1, b2, b3, bAddr0 + (1024 + k0 + kl) * 2);
                    mma16816(acc,     a0, a1, a2, a3, b0, b1);
                    mma16816(acc + 4, a0, a1, a2, a3, b2, b3);
                }
            }
        }

        // ---- park z tile in smem ----
        {
            const int fg = lane >> 2, ft = lane & 3;
            #pragma unroll
            for (int blk = 0; blk < 2; blk++) {
                int ncol = nbase + blk * 8 + 2 * ft;
                z_s[(m0 + fg)     * 33 + ncol]     = acc[blk * 4 + 0];
                z_s[(m0 + fg)     * 33 + ncol + 1] = acc[blk * 4 + 1];
                z_s[(m0 + fg + 8) * 33 + ncol]     = acc[blk * 4 + 2];
                z_s[(m0 + fg + 8) * 33 + ncol + 1] = acc[blk * 4 + 3];
            }
        }
        __syncthreads();

        // ---- gates: thread owns (b=gb, j = cta*8 + gj..+1) ----
        {
            const float* xzr = g_xz + (size_t)t * (BATCH * GDIM) + (size_t)gb * GDIM + cta * 8 + gj;
            const bool msk = (seq[gb * SEQLEN + t] != 0);
            const float* zr = z_s + gb * 33;
            #pragma unroll
            for (int q = 0; q < 2; q++) {
                int jl = gj + q;
                float zi = zr[jl]      + xzr[q];
                float zf = zr[8 + jl]  + xzr[1024 + q];
                float zg = zr[16 + jl] + xzr[2048 + q];
                float zo = zr[24 + jl] + xzr[3072 + q];
                float ig  = 1.f / (1.f + expf(-zi));
                float fgt = 1.f / (1.f + expf(-zf));
                float gg  = tanhf(zg);
                float og  = 1.f / (1.f + expf(-zo));
                float cn = fgt * c_r[q] + ig * gg;
                float hn = og * tanhf(cn);
                if (msk) { c_r[q] = cn; h_r[q] = hn; }
            }
            union { __nv_bfloat16 b[2]; uint32_t u; } hiP, loP;
            #pragma unroll
            for (int q = 0; q < 2; q++) {
                __nv_bfloat16 hi = __float2bfloat16(h_r[q]);
                hiP.b[q] = hi;
                loP.b[q] = __float2bfloat16(h_r[q] - __bfloat162float(hi));
            }
            __nv_bfloat16* hN = g_hsplit[p ^ 1];
            *(uint32_t*)&hN[(size_t)gb * 1024 + cta * 8 + gj]         = hiP.u;
            *(uint32_t*)&hN[65536 + (size_t)gb * 1024 + cta * 8 + gj] = loP.u;
        }

        p ^= 1;
        grid_barrier();
    }

    // final h -> out[b][1024]
    *(float2*)&out[(size_t)gb * HIDDEN + cta * 8 + gj] = make_float2(h_r[0], h_r[1]);
}

// ---------------- launch ----------------
extern "C" void kernel_launch(void* const* d_in, const int* in_sizes, int n_in,
                              void* d_out, int out_size) {
    const float* emb  = nullptr;
    const float* W    = nullptr;
    const float* Rm   = nullptr;
    const float* bias = nullptr;
    const int*   seq  = nullptr;
    for (int i = 0; i < n_in; i++) {
        switch (in_sizes[i]) {
            case VOCAB * EMBED:  emb  = (const float*)d_in[i]; break;
            case EMBED * GDIM:   W    = (const float*)d_in[i]; break;
            case HIDDEN * GDIM:  Rm   = (const float*)d_in[i]; break;
            case GDIM:           bias = (const float*)d_in[i]; break;
            case BATCH * SEQLEN: seq  = (const int*)d_in[i];   break;
        }
    }
    (void)out_size;

    cudaFuncSetAttribute(lstm_mma_kernel, cudaFuncAttributeMaxDynamicSharedMemorySize, SMEM2);

    hinit_kernel<<<64, 256>>>();
    rsplit_kernel<<<(int)(((size_t)NCTA2 * 32 * 2048 + 255) / 256), 256>>>(Rm);
    dim3 g1(GDIM / 64, (SEQLEN * BATCH) / 64);
    xz_gemm_kernel<<<g1, 256>>>(emb, W, bias, seq);
    lstm_mma_kernel<<<NCTA2, TPB2, SMEM2>>>(seq, (float*)d_out);
}